// round 1
// baseline (speedup 1.0000x reference)
#include <cuda_runtime.h>

#define GRIDX 128
#define NPTS (GRIDX * GRIDX)
#define HID 64
#define BATCH 64
#define IPB 256                 // grid points per block
#define BLOCKS_I (NPTS / IPB)   // 64 blocks along i per batch

// Partial sums: one float per (batch, i-block). Device global scratch (no allocs allowed).
__device__ float g_partials[BATCH * BLOCKS_I];

__device__ __forceinline__ unsigned long long pack2(float lo, float hi) {
    unsigned long long r;
    asm("mov.b64 %0, {%1, %2};" : "=l"(r) : "f"(lo), "f"(hi));
    return r;
}
__device__ __forceinline__ void unpack2(unsigned long long v, float& lo, float& hi) {
    asm("mov.b64 {%0, %1}, %2;" : "=f"(lo), "=f"(hi) : "l"(v));
}
// Blackwell packed fp32 FMA (SASS FFMA2): 2x fp32 FMA throughput, full fp32 precision.
__device__ __forceinline__ unsigned long long ffma2(unsigned long long a,
                                                    unsigned long long b,
                                                    unsigned long long c) {
    unsigned long long d;
    asm("fma.rn.f32x2 %0, %1, %2, %3;" : "=l"(d) : "l"(a), "l"(b), "l"(c));
    return d;
}

__global__ __launch_bounds__(IPB) void gauge_main(
    const float* __restrict__ x,       // (B, N, 2)
    const float* __restrict__ H,       // (2, 2)
    const float* __restrict__ W_emb,   // (4, HID)
    const float* __restrict__ b_emb,   // (HID)
    const float* __restrict__ W_hid,   // (HID, HID)
    const float* __restrict__ b_hid,   // (HID)
    const float* __restrict__ W_post)  // (HID, 1)
{
    __shared__ __align__(16) float sW[HID * HID];  // W_hid, row j contiguous in k
    __shared__ __align__(16) float sWe[4 * HID];
    __shared__ float sbe[HID];
    __shared__ __align__(8) float sbh[HID];
    __shared__ float sWp[HID];
    __shared__ float sH[4];
    __shared__ float wsum[IPB / 32];

    const int tid = threadIdx.x;

    // Stage weights into shared
    for (int i4 = tid; i4 < HID * HID / 4; i4 += IPB)
        ((float4*)sW)[i4] = ((const float4*)W_hid)[i4];
    for (int i4 = tid; i4 < 4 * HID / 4; i4 += IPB)
        ((float4*)sWe)[i4] = ((const float4*)W_emb)[i4];
    if (tid < HID) { sbe[tid] = b_emb[tid]; sbh[tid] = b_hid[tid]; sWp[tid] = W_post[tid]; }
    if (tid < 4) sH[tid] = H[tid];
    __syncthreads();

    const int b = blockIdx.y;
    const int i = blockIdx.x * IPB + tid;
    const float2* xb = (const float2*)x + (size_t)b * NPTS;

    // Torus neighbor indices (match numpy: up=(y+1)%G, down=(y-1)%G, left=(x-1)%G, right=(x+1)%G)
    const int xc = i & (GRIDX - 1);
    const int yc = i >> 7;
    const int iu  = xc + (((yc + 1) & (GRIDX - 1)) << 7);
    const int idn = xc + (((yc - 1) & (GRIDX - 1)) << 7);
    const int il  = ((xc - 1) & (GRIDX - 1)) + (yc << 7);
    const int ir  = ((xc + 1) & (GRIDX - 1)) + (yc << 7);

    const float2 xi = xb[i];
    const float2 xu = xb[iu], xd = xb[idn], xl = xb[il], xr = xb[ir];

    // v[n] = sum_m x[m] * H[m][n]
    const float v0 = xi.x * sH[0] + xi.y * sH[2];
    const float v1 = xi.x * sH[1] + xi.y * sH[3];
    const float s0 = v0 * xu.x + v1 * xu.y;  // up
    const float s1 = v0 * xd.x + v1 * xd.y;  // down
    const float s2 = v0 * xl.x + v1 * xl.y;  // left
    const float s3 = v0 * xr.x + v1 * xr.y;  // right

    // h2 accumulators as 32 packed f32x2 (64 regs), init with b_hid
    unsigned long long acc[HID / 2];
    #pragma unroll
    for (int p = 0; p < HID / 2; p++)
        acc[p] = ((const unsigned long long*)sbh)[p];

    // Fused layer1 + layer2: compute h1[j] on the fly, rank-1 update of acc.
    #pragma unroll 8
    for (int j = 0; j < HID; j++) {
        float a = sbe[j];
        a = fmaf(s0, sWe[j], a);
        a = fmaf(s1, sWe[HID + j], a);
        a = fmaf(s2, sWe[2 * HID + j], a);
        a = fmaf(s3, sWe[3 * HID + j], a);
        a = fmaxf(a, 0.0f);
        const unsigned long long aj = pack2(a, a);
        const ulonglong2* w = (const ulonglong2*)(&sW[j * HID]);
        #pragma unroll
        for (int kk = 0; kk < HID / 4; kk++) {
            const ulonglong2 wv = w[kk];             // 4 weights via LDS.128 (broadcast)
            acc[2 * kk]     = ffma2(aj, wv.x, acc[2 * kk]);
            acc[2 * kk + 1] = ffma2(aj, wv.y, acc[2 * kk + 1]);
        }
    }

    // relu + dot with W_post
    float sum = 0.0f;
    #pragma unroll
    for (int p = 0; p < HID / 2; p++) {
        float lo, hi;
        unpack2(acc[p], lo, hi);
        sum = fmaf(fmaxf(lo, 0.0f), sWp[2 * p], sum);
        sum = fmaf(fmaxf(hi, 0.0f), sWp[2 * p + 1], sum);
    }

    // Deterministic block reduction (fixed order)
    #pragma unroll
    for (int o = 16; o > 0; o >>= 1)
        sum += __shfl_down_sync(0xffffffffu, sum, o);
    if ((tid & 31) == 0) wsum[tid >> 5] = sum;
    __syncthreads();
    if (tid == 0) {
        float t = 0.0f;
        #pragma unroll
        for (int w8 = 0; w8 < IPB / 32; w8++) t += wsum[w8];
        g_partials[b * BLOCKS_I + blockIdx.x] = t;
    }
}

__global__ void gauge_reduce(const float* __restrict__ b_post, float* __restrict__ out) {
    const int b = blockIdx.x;
    const int t = threadIdx.x;  // BLOCKS_I = 64 threads
    float v = g_partials[b * BLOCKS_I + t];
    #pragma unroll
    for (int o = 16; o > 0; o >>= 1)
        v += __shfl_down_sync(0xffffffffu, v, o);
    __shared__ float ws[2];
    if ((t & 31) == 0) ws[t >> 5] = v;
    __syncthreads();
    if (t == 0)
        out[b] = ws[0] + ws[1] + (float)NPTS * b_post[0];
}

extern "C" void kernel_launch(void* const* d_in, const int* in_sizes, int n_in,
                              void* d_out, int out_size) {
    (void)in_sizes; (void)n_in; (void)out_size;
    const float* x      = (const float*)d_in[0];
    const float* H      = (const float*)d_in[1];
    const float* W_emb  = (const float*)d_in[2];
    const float* b_emb  = (const float*)d_in[3];
    const float* W_hid  = (const float*)d_in[4];
    const float* b_hid  = (const float*)d_in[5];
    const float* W_post = (const float*)d_in[6];
    const float* b_post = (const float*)d_in[7];

    dim3 grid(BLOCKS_I, BATCH);
    gauge_main<<<grid, IPB>>>(x, H, W_emb, b_emb, W_hid, b_hid, W_post);
    gauge_reduce<<<BATCH, BLOCKS_I>>>(b_post, (float*)d_out);
}

// round 3
// speedup vs baseline: 2.0803x; 2.0803x over previous
#include <cuda_runtime.h>
#include <cuda_bf16.h>
#include <cstdint>

#define GRIDX 128
#define NPTS (GRIDX * GRIDX)
#define HID 64
#define BATCH 64
#define TILE_M 128
#define TILES_PER_CTA 8
#define CTAS_PER_BATCH 16            // 16 * 8 * 128 = 16384 points per batch
#define NCTAS (BATCH * CTAS_PER_BATCH)
#define THREADS 128

// SMEM offsets from 1024-aligned base
#define SM_BHI 0                     // B hi: 64 rows(n) x 128B (k-cols, swizzled)
#define SM_BLO 8192
#define SM_AHI 16384                 // A hi: 128 rows(m) x 128B
#define SM_ALO 32768
#define SM_MISC 49152                // +0 wsum[4], +64 wp[64], +320 bh[64]
#define SMEM_BYTES (49152 + 576 + 1024)

#define SWZ(o) ((o) ^ (((o) >> 3) & 0x70))

__device__ float g_partials[NCTAS];

static __device__ __forceinline__ uint32_t smem_u32(const void* p) {
    uint32_t a;
    asm("{ .reg .u64 t; cvta.to.shared.u64 t, %1; cvt.u32.u64 %0, t; }" : "=r"(a) : "l"(p));
    return a;
}
static __device__ __forceinline__ void sts32(uint32_t addr, uint32_t v) {
    asm volatile("st.shared.b32 [%0], %1;" :: "r"(addr), "r"(v) : "memory");
}
static __device__ __forceinline__ unsigned long long pack2(float lo, float hi) {
    unsigned long long r;
    asm("mov.b64 %0, {%1, %2};" : "=l"(r) : "f"(lo), "f"(hi));
    return r;
}
static __device__ __forceinline__ void unpack2(unsigned long long v, float& lo, float& hi) {
    asm("mov.b64 {%0, %1}, %2;" : "=f"(lo), "=f"(hi) : "l"(v));
}
static __device__ __forceinline__ unsigned long long ffma2(unsigned long long a,
                                                            unsigned long long b,
                                                            unsigned long long c) {
    unsigned long long d;
    asm("fma.rn.f32x2 %0, %1, %2, %3;" : "=l"(d) : "l"(a), "l"(b), "l"(c));
    return d;
}
// pack {hi_elem, lo_elem} -> bf16x2 (lo half holds lo_elem)
static __device__ __forceinline__ uint32_t cvt_bf16x2(float hi, float lo) {
    uint32_t r;
    asm("cvt.rn.bf16x2.f32 %0, %1, %2;" : "=r"(r) : "f"(hi), "f"(lo));
    return r;
}
static __device__ __forceinline__ void bf16x2_f32(uint32_t v, float& lo, float& hi) {
    lo = __uint_as_float(v << 16);
    hi = __uint_as_float(v & 0xffff0000u);
}
static __device__ __forceinline__ void ldsm_x4(uint32_t addr, uint32_t& r0, uint32_t& r1,
                                               uint32_t& r2, uint32_t& r3) {
    asm volatile("ldmatrix.sync.aligned.m8n8.x4.shared.b16 {%0,%1,%2,%3}, [%4];"
                 : "=r"(r0), "=r"(r1), "=r"(r2), "=r"(r3) : "r"(addr));
}
static __device__ __forceinline__ void mma16816(float* c, const uint32_t* a, const uint32_t* b) {
    asm volatile(
        "mma.sync.aligned.m16n8k16.row.col.f32.bf16.bf16.f32 "
        "{%0,%1,%2,%3}, {%4,%5,%6,%7}, {%8,%9}, {%0,%1,%2,%3};"
        : "+f"(c[0]), "+f"(c[1]), "+f"(c[2]), "+f"(c[3])
        : "r"(a[0]), "r"(a[1]), "r"(a[2]), "r"(a[3]), "r"(b[0]), "r"(b[1]));
}

__global__ __launch_bounds__(THREADS)
void gauge_tc(const float* __restrict__ x, const float* __restrict__ H,
              const float* __restrict__ W_emb, const float* __restrict__ b_emb,
              const float* __restrict__ W_hid, const float* __restrict__ b_hid,
              const float* __restrict__ W_post) {
    extern __shared__ __align__(1024) char smraw[];
    const uint32_t sb0 = smem_u32(smraw);
    const uint32_t sb = (sb0 + 1023u) & ~1023u;
    char* smc = smraw + (sb - sb0);

    const int tid = threadIdx.x;
    const int wid = tid >> 5;
    const int lid = tid & 31;

    // Stage W_post + b_hid
    if (tid < HID) {
        *(float*)(smc + SM_MISC + 64 + tid * 4) = W_post[tid];
        *(float*)(smc + SM_MISC + 320 + tid * 4) = b_hid[tid];
    }

    // Build B tiles: Bsm[n][k=j] = W_hid[j][n], split hi/lo bf16, swizzled rows of 128B.
    #pragma unroll
    for (int kq = 0; kq < 16; kq++) {
        const int idx = tid + kq * 128;       // 0..2047
        const int n = idx & 63;
        const int jp = idx >> 6;              // j pair 0..31
        const float w0 = __ldg(W_hid + (2 * jp) * HID + n);
        const float w1 = __ldg(W_hid + (2 * jp + 1) * HID + n);
        const uint32_t hi2 = cvt_bf16x2(w1, w0);
        float r0, r1;
        bf16x2_f32(hi2, r0, r1);
        const uint32_t lo2 = cvt_bf16x2(w1 - r1, w0 - r0);
        const uint32_t off = SWZ((uint32_t)(n * 128 + jp * 4));
        sts32(sb + SM_BHI + off, hi2);
        sts32(sb + SM_BLO + off, lo2);
    }
    __syncthreads();

    // Per-lane layer-1 weights: lane owns h1 columns 2l, 2l+1
    const int col2 = lid * 2;
    const float2 e0 = __ldg((const float2*)(W_emb + 0 * HID + col2));
    const float2 e1 = __ldg((const float2*)(W_emb + 1 * HID + col2));
    const float2 e2 = __ldg((const float2*)(W_emb + 2 * HID + col2));
    const float2 e3 = __ldg((const float2*)(W_emb + 3 * HID + col2));
    const float2 eb = __ldg((const float2*)(b_emb + col2));
    const unsigned long long we0 = pack2(e0.x, e0.y);
    const unsigned long long we1 = pack2(e1.x, e1.y);
    const unsigned long long we2 = pack2(e2.x, e2.y);
    const unsigned long long we3 = pack2(e3.x, e3.y);
    const unsigned long long be2 = pack2(eb.x, eb.y);
    const float h00 = __ldg(H + 0), h01 = __ldg(H + 1), h10 = __ldg(H + 2), h11 = __ldg(H + 3);

    const int cta = blockIdx.x;
    const int b = cta >> 4;
    const int sub = cta & 15;
    const float2* xb = (const float2*)x + (size_t)b * NPTS;

    const float2* wp2 = (const float2*)(smc + SM_MISC + 64);
    const float2* bh2 = (const float2*)(smc + SM_MISC + 320);

    const int warpbase = wid * 32;

    // Precompute ldmatrix lane addresses (constant across tiles/k except k-offset)
    // A frag: mat = lid>>3; row = warpbase + mt*16 + (mat&1)*8 + (lid&7); colByte = k*32 + (mat>>1)*16
    const int amat = lid >> 3;
    const int arow_base = warpbase + (amat & 1) * 8 + (lid & 7);
    const int acol_half = (amat >> 1) * 16;
    // B frag: nt = ntp*2 + (mat>>1); n = nt*8 + (lid&7); colByte = k*32 + (mat&1)*16
    const int bn_half = (amat >> 1);           // adds 1 to nt
    const int bcol_half = (amat & 1) * 16;
    const int bn_sub = lid & 7;

    float acc_out = 0.0f;

    for (int tt = 0; tt < TILES_PER_CTA; tt++) {
        const int base = (sub * TILES_PER_CTA + tt) * TILE_M;
        const int i = base + tid;

        // gauge contraction
        const int xc = i & (GRIDX - 1);
        const int yc = i >> 7;
        const int iu = xc + (((yc + 1) & (GRIDX - 1)) << 7);
        const int idn = xc + (((yc - 1) & (GRIDX - 1)) << 7);
        const int il = ((xc - 1) & (GRIDX - 1)) + (yc << 7);
        const int ir = ((xc + 1) & (GRIDX - 1)) + (yc << 7);
        const float2 xi = xb[i];
        const float2 xu = xb[iu], xd = xb[idn], xl = xb[il], xr = xb[ir];
        const float v0 = xi.x * h00 + xi.y * h10;
        const float v1 = xi.x * h01 + xi.y * h11;
        const float s0 = v0 * xu.x + v1 * xu.y;
        const float s1 = v0 * xd.x + v1 * xd.y;
        const float s2 = v0 * xl.x + v1 * xl.y;
        const float s3 = v0 * xr.x + v1 * xr.y;

        __syncwarp();  // protect A buffer from previous iteration's ldmatrix

        // Layer 1 + bf16 hi/lo split + swizzled STS (lane = column pair, q = point)
        #pragma unroll 8
        for (int q = 0; q < 32; q++) {
            const float bs0 = __shfl_sync(0xffffffffu, s0, q);
            const float bs1 = __shfl_sync(0xffffffffu, s1, q);
            const float bs2 = __shfl_sync(0xffffffffu, s2, q);
            const float bs3 = __shfl_sync(0xffffffffu, s3, q);
            unsigned long long a2 = be2;
            a2 = ffma2(pack2(bs0, bs0), we0, a2);
            a2 = ffma2(pack2(bs1, bs1), we1, a2);
            a2 = ffma2(pack2(bs2, bs2), we2, a2);
            a2 = ffma2(pack2(bs3, bs3), we3, a2);
            float a0, a1;
            unpack2(a2, a0, a1);
            a0 = fmaxf(a0, 0.0f);
            a1 = fmaxf(a1, 0.0f);
            const uint32_t hi2 = cvt_bf16x2(a1, a0);
            float r0, r1;
            bf16x2_f32(hi2, r0, r1);
            const uint32_t lo2 = cvt_bf16x2(a1 - r1, a0 - r0);
            const int m = warpbase + q;
            const uint32_t off = (uint32_t)(m * 128) +
                (((uint32_t)(lid * 4)) ^ (((uint32_t)(m & 7)) << 4));
            sts32(sb + SM_AHI + off, hi2);
            sts32(sb + SM_ALO + off, lo2);
        }
        __syncwarp();

        // Accumulators: 2 m-tiles x 8 n-tiles x 4
        float acc[2][8][4];
        #pragma unroll
        for (int mt = 0; mt < 2; mt++)
            #pragma unroll
            for (int nt = 0; nt < 8; nt++)
                #pragma unroll
                for (int e = 0; e < 4; e++)
                    acc[mt][nt][e] = 0.0f;

        #pragma unroll
        for (int k = 0; k < 4; k++) {
            // A fragments (hi, lo) for 2 m-tiles
            uint32_t ahi[2][4], alo[2][4];
            #pragma unroll
            for (int mt = 0; mt < 2; mt++) {
                const int row = arow_base + mt * 16;
                const uint32_t cb = (uint32_t)(k * 32 + acol_half);
                const uint32_t off = (uint32_t)(row * 128) + (cb ^ (((uint32_t)(row & 7)) << 4));
                ldsm_x4(sb + SM_AHI + off, ahi[mt][0], ahi[mt][1], ahi[mt][2], ahi[mt][3]);
                ldsm_x4(sb + SM_ALO + off, alo[mt][0], alo[mt][1], alo[mt][2], alo[mt][3]);
            }
            // B fragments (hi, lo) for 8 n-tiles
            uint32_t bhi[8][2], blo[8][2];
            #pragma unroll
            for (int ntp = 0; ntp < 4; ntp++) {
                const int nt = ntp * 2 + bn_half;
                const int n = nt * 8 + bn_sub;
                const uint32_t cb = (uint32_t)(k * 32 + bcol_half);
                const uint32_t off = (uint32_t)(n * 128) + (cb ^ (((uint32_t)(n & 7)) << 4));
                ldsm_x4(sb + SM_BHI + off,
                        bhi[2 * ntp][0], bhi[2 * ntp][1], bhi[2 * ntp + 1][0], bhi[2 * ntp + 1][1]);
                ldsm_x4(sb + SM_BLO + off,
                        blo[2 * ntp][0], blo[2 * ntp][1], blo[2 * ntp + 1][0], blo[2 * ntp + 1][1]);
            }
            // 3-term split MMA
            #pragma unroll
            for (int mt = 0; mt < 2; mt++)
                #pragma unroll
                for (int nt = 0; nt < 8; nt++) {
                    mma16816(acc[mt][nt], ahi[mt], bhi[nt]);
                    mma16816(acc[mt][nt], ahi[mt], blo[nt]);
                    mma16816(acc[mt][nt], alo[mt], bhi[nt]);
                }
        }

        // Epilogue: +b_hid, relu, dot W_post (cols c = nt*8 + 2*(lid&3) + {0,1})
        float tsum = 0.0f;
        #pragma unroll
        for (int nt = 0; nt < 8; nt++) {
            const float2 bh = bh2[nt * 4 + (lid & 3)];
            const float2 wp = wp2[nt * 4 + (lid & 3)];
            #pragma unroll
            for (int mt = 0; mt < 2; mt++) {
                tsum = fmaf(fmaxf(acc[mt][nt][0] + bh.x, 0.0f), wp.x, tsum);
                tsum = fmaf(fmaxf(acc[mt][nt][1] + bh.y, 0.0f), wp.y, tsum);
                tsum = fmaf(fmaxf(acc[mt][nt][2] + bh.x, 0.0f), wp.x, tsum);
                tsum = fmaf(fmaxf(acc[mt][nt][3] + bh.y, 0.0f), wp.y, tsum);
            }
        }
        acc_out += tsum;
    }

    // Deterministic reduction: warp, then block
    float v = acc_out;
    #pragma unroll
    for (int o = 16; o > 0; o >>= 1)
        v += __shfl_down_sync(0xffffffffu, v, o);
    if (lid == 0)
        *(float*)(smc + SM_MISC + wid * 4) = v;
    __syncthreads();
    if (tid == 0) {
        float t = 0.0f;
        #pragma unroll
        for (int w = 0; w < 4; w++)
            t += *(float*)(smc + SM_MISC + w * 4);
        g_partials[cta] = t;
    }
}

__global__ void gauge_reduce(const float* __restrict__ b_post, float* __restrict__ out) {
    const int b = blockIdx.x;
    const int t = threadIdx.x;  // 32 threads
    float v = (t < CTAS_PER_BATCH) ? g_partials[b * CTAS_PER_BATCH + t] : 0.0f;
    #pragma unroll
    for (int o = 16; o > 0; o >>= 1)
        v += __shfl_down_sync(0xffffffffu, v, o);
    if (t == 0)
        out[b] = v + (float)NPTS * b_post[0];
}

extern "C" void kernel_launch(void* const* d_in, const int* in_sizes, int n_in,
                              void* d_out, int out_size) {
    (void)in_sizes; (void)n_in; (void)out_size;
    const float* x      = (const float*)d_in[0];
    const float* H      = (const float*)d_in[1];
    const float* W_emb  = (const float*)d_in[2];
    const float* b_emb  = (const float*)d_in[3];
    const float* W_hid  = (const float*)d_in[4];
    const float* b_hid  = (const float*)d_in[5];
    const float* W_post = (const float*)d_in[6];
    const float* b_post = (const float*)d_in[7];

    cudaFuncSetAttribute(gauge_tc, cudaFuncAttributeMaxDynamicSharedMemorySize, SMEM_BYTES);
    gauge_tc<<<NCTAS, THREADS, SMEM_BYTES>>>(x, H, W_emb, b_emb, W_hid, b_hid, W_post);
    gauge_reduce<<<BATCH, 32>>>(b_post, (float*)d_out);
}

// round 4
// speedup vs baseline: 4.1362x; 1.9883x over previous
#include <cuda_runtime.h>
#include <cuda_fp16.h>
#include <cstdint>

#define GRIDX 128
#define NPTS (GRIDX * GRIDX)
#define HID 64
#define BATCH 64
#define TILE_M 128
#define TILES_PER_CTA 8
#define CTAS_PER_BATCH 16            // 16 * 8 * 128 = 16384 points per batch
#define NCTAS (BATCH * CTAS_PER_BATCH)
#define THREADS 128

// SMEM offsets from 1024-aligned base
#define SM_BHI 0                     // B hi: 64 rows(n) x 128B (k-cols, swizzled), fp16
#define SM_BLO 8192
#define SM_AHI 16384                 // A: 128 rows(m) x 128B, fp16
#define SM_MISC 32768                // +0 wsum[4], +64 wp[64], +320 bh[64]
#define SMEM_BYTES (32768 + 576 + 1024)

#define SWZ(o) ((o) ^ (((o) >> 3) & 0x70))

__device__ float g_partials[NCTAS];
__device__ int g_count[BATCH];       // zero-init; self-resets each launch

static __device__ __forceinline__ uint32_t smem_u32(const void* p) {
    uint32_t a;
    asm("{ .reg .u64 t; cvta.to.shared.u64 t, %1; cvt.u32.u64 %0, t; }" : "=r"(a) : "l"(p));
    return a;
}
static __device__ __forceinline__ void sts32(uint32_t addr, uint32_t v) {
    asm volatile("st.shared.b32 [%0], %1;" :: "r"(addr), "r"(v) : "memory");
}
static __device__ __forceinline__ unsigned long long pack2(float lo, float hi) {
    unsigned long long r;
    asm("mov.b64 %0, {%1, %2};" : "=l"(r) : "f"(lo), "f"(hi));
    return r;
}
static __device__ __forceinline__ void unpack2(unsigned long long v, float& lo, float& hi) {
    asm("mov.b64 {%0, %1}, %2;" : "=f"(lo), "=f"(hi) : "l"(v));
}
static __device__ __forceinline__ unsigned long long ffma2(unsigned long long a,
                                                            unsigned long long b,
                                                            unsigned long long c) {
    unsigned long long d;
    asm("fma.rn.f32x2 %0, %1, %2, %3;" : "=l"(d) : "l"(a), "l"(b), "l"(c));
    return d;
}
// pack {hi_elem -> upper half, lo_elem -> lower half} as f16x2
static __device__ __forceinline__ uint32_t cvt_f16x2(float hi, float lo) {
    uint32_t r;
    asm("cvt.rn.f16x2.f32 %0, %1, %2;" : "=r"(r) : "f"(hi), "f"(lo));
    return r;
}
static __device__ __forceinline__ void ldsm_x4(uint32_t addr, uint32_t& r0, uint32_t& r1,
                                               uint32_t& r2, uint32_t& r3) {
    asm volatile("ldmatrix.sync.aligned.m8n8.x4.shared.b16 {%0,%1,%2,%3}, [%4];"
                 : "=r"(r0), "=r"(r1), "=r"(r2), "=r"(r3) : "r"(addr));
}
static __device__ __forceinline__ void mma16816(float* c, const uint32_t* a, const uint32_t* b) {
    asm volatile(
        "mma.sync.aligned.m16n8k16.row.col.f32.f16.f16.f32 "
        "{%0,%1,%2,%3}, {%4,%5,%6,%7}, {%8,%9}, {%0,%1,%2,%3};"
        : "+f"(c[0]), "+f"(c[1]), "+f"(c[2]), "+f"(c[3])
        : "r"(a[0]), "r"(a[1]), "r"(a[2]), "r"(a[3]), "r"(b[0]), "r"(b[1]));
}

__global__ __launch_bounds__(THREADS)
void gauge_tc(const float* __restrict__ x, const float* __restrict__ H,
              const float* __restrict__ W_emb, const float* __restrict__ b_emb,
              const float* __restrict__ W_hid, const float* __restrict__ b_hid,
              const float* __restrict__ W_post, const float* __restrict__ b_post,
              float* __restrict__ out) {
    extern __shared__ __align__(1024) char smraw[];
    const uint32_t sb0 = smem_u32(smraw);
    const uint32_t sb = (sb0 + 1023u) & ~1023u;
    char* smc = smraw + (sb - sb0);

    const int tid = threadIdx.x;
    const int wid = tid >> 5;
    const int lid = tid & 31;

    // Stage W_post + b_hid
    if (tid < HID) {
        *(float*)(smc + SM_MISC + 64 + tid * 4) = W_post[tid];
        *(float*)(smc + SM_MISC + 320 + tid * 4) = b_hid[tid];
    }

    // Build B tiles: Bsm[n][k=j] = W_hid[j][n], split hi/lo fp16, swizzled 128B rows.
    #pragma unroll
    for (int kq = 0; kq < 16; kq++) {
        const int idx = tid + kq * 128;       // 0..2047
        const int n = idx & 63;
        const int jp = idx >> 6;              // j pair 0..31
        const float w0 = __ldg(W_hid + (2 * jp) * HID + n);
        const float w1 = __ldg(W_hid + (2 * jp + 1) * HID + n);
        const uint32_t hi2 = cvt_f16x2(w1, w0);
        const float r0 = __half2float(__ushort_as_half((unsigned short)(hi2 & 0xffff)));
        const float r1 = __half2float(__ushort_as_half((unsigned short)(hi2 >> 16)));
        const uint32_t lo2 = cvt_f16x2(w1 - r1, w0 - r0);
        const uint32_t off = SWZ((uint32_t)(n * 128 + jp * 4));
        sts32(sb + SM_BHI + off, hi2);
        sts32(sb + SM_BLO + off, lo2);
    }
    __syncthreads();

    // Per-lane layer-1 weights: lane owns h1 columns 2l, 2l+1
    const int col2 = lid * 2;
    const float2 e0 = __ldg((const float2*)(W_emb + 0 * HID + col2));
    const float2 e1 = __ldg((const float2*)(W_emb + 1 * HID + col2));
    const float2 e2 = __ldg((const float2*)(W_emb + 2 * HID + col2));
    const float2 e3 = __ldg((const float2*)(W_emb + 3 * HID + col2));
    const float2 eb = __ldg((const float2*)(b_emb + col2));
    const unsigned long long we0 = pack2(e0.x, e0.y);
    const unsigned long long we1 = pack2(e1.x, e1.y);
    const unsigned long long we2 = pack2(e2.x, e2.y);
    const unsigned long long we3 = pack2(e3.x, e3.y);
    const unsigned long long be2 = pack2(eb.x, eb.y);
    const float h00 = __ldg(H + 0), h01 = __ldg(H + 1), h10 = __ldg(H + 2), h11 = __ldg(H + 3);

    const int cta = blockIdx.x;
    const int b = cta >> 4;
    const int sub = cta & 15;
    const float2* xb = (const float2*)x + (size_t)b * NPTS;

    const float2* wp2 = (const float2*)(smc + SM_MISC + 64);
    const float2* bh2 = (const float2*)(smc + SM_MISC + 320);

    const int warpbase = wid * 32;

    // ldmatrix lane addressing
    const int amat = lid >> 3;
    const int arow_base = warpbase + (amat & 1) * 8 + (lid & 7);
    const int acol_half = (amat >> 1) * 16;
    const int bn_half = (amat >> 1);
    const int bcol_half = (amat & 1) * 16;
    const int bn_sub = lid & 7;

    float acc_out = 0.0f;

    for (int tt = 0; tt < TILES_PER_CTA; tt++) {
        const int base = (sub * TILES_PER_CTA + tt) * TILE_M;
        const int i = base + tid;

        // gauge contraction
        const int xc = i & (GRIDX - 1);
        const int yc = i >> 7;
        const int iu = xc + (((yc + 1) & (GRIDX - 1)) << 7);
        const int idn = xc + (((yc - 1) & (GRIDX - 1)) << 7);
        const int il = ((xc - 1) & (GRIDX - 1)) + (yc << 7);
        const int ir = ((xc + 1) & (GRIDX - 1)) + (yc << 7);
        const float2 xi = xb[i];
        const float2 xu = xb[iu], xd = xb[idn], xl = xb[il], xr = xb[ir];
        const float v0 = xi.x * h00 + xi.y * h10;
        const float v1 = xi.x * h01 + xi.y * h11;
        const float s0 = v0 * xu.x + v1 * xu.y;
        const float s1 = v0 * xd.x + v1 * xd.y;
        const float s2 = v0 * xl.x + v1 * xl.y;
        const float s3 = v0 * xr.x + v1 * xr.y;

        __syncwarp();  // A buffer reuse guard vs previous iteration's ldmatrix

        // Layer 1: compute h1 pair, relu, fp16 pack, swizzled STS (lane = col pair)
        #pragma unroll 8
        for (int q = 0; q < 32; q++) {
            const float bs0 = __shfl_sync(0xffffffffu, s0, q);
            const float bs1 = __shfl_sync(0xffffffffu, s1, q);
            const float bs2 = __shfl_sync(0xffffffffu, s2, q);
            const float bs3 = __shfl_sync(0xffffffffu, s3, q);
            unsigned long long a2 = be2;
            a2 = ffma2(pack2(bs0, bs0), we0, a2);
            a2 = ffma2(pack2(bs1, bs1), we1, a2);
            a2 = ffma2(pack2(bs2, bs2), we2, a2);
            a2 = ffma2(pack2(bs3, bs3), we3, a2);
            float a0, a1;
            unpack2(a2, a0, a1);
            a0 = fmaxf(a0, 0.0f);
            a1 = fmaxf(a1, 0.0f);
            const uint32_t p16 = cvt_f16x2(a1, a0);
            const int m = warpbase + q;
            const uint32_t off = (uint32_t)(m * 128) +
                (((uint32_t)(lid * 4)) ^ (((uint32_t)(m & 7)) << 4));
            sts32(sb + SM_AHI + off, p16);
        }
        __syncwarp();

        float acc[2][8][4];
        #pragma unroll
        for (int mt = 0; mt < 2; mt++)
            #pragma unroll
            for (int nt = 0; nt < 8; nt++)
                #pragma unroll
                for (int e = 0; e < 4; e++)
                    acc[mt][nt][e] = 0.0f;

        #pragma unroll
        for (int k = 0; k < 4; k++) {
            uint32_t af[2][4];
            #pragma unroll
            for (int mt = 0; mt < 2; mt++) {
                const int row = arow_base + mt * 16;
                const uint32_t cb = (uint32_t)(k * 32 + acol_half);
                const uint32_t off = (uint32_t)(row * 128) + (cb ^ (((uint32_t)(row & 7)) << 4));
                ldsm_x4(sb + SM_AHI + off, af[mt][0], af[mt][1], af[mt][2], af[mt][3]);
            }
            uint32_t bhi[8][2], blo[8][2];
            #pragma unroll
            for (int ntp = 0; ntp < 4; ntp++) {
                const int nt = ntp * 2 + bn_half;
                const int n = nt * 8 + bn_sub;
                const uint32_t cb = (uint32_t)(k * 32 + bcol_half);
                const uint32_t off = (uint32_t)(n * 128) + (cb ^ (((uint32_t)(n & 7)) << 4));
                ldsm_x4(sb + SM_BHI + off,
                        bhi[2 * ntp][0], bhi[2 * ntp][1], bhi[2 * ntp + 1][0], bhi[2 * ntp + 1][1]);
                ldsm_x4(sb + SM_BLO + off,
                        blo[2 * ntp][0], blo[2 * ntp][1], blo[2 * ntp + 1][0], blo[2 * ntp + 1][1]);
            }
            #pragma unroll
            for (int mt = 0; mt < 2; mt++)
                #pragma unroll
                for (int nt = 0; nt < 8; nt++) {
                    mma16816(acc[mt][nt], af[mt], bhi[nt]);
                    mma16816(acc[mt][nt], af[mt], blo[nt]);
                }
        }

        // Epilogue: +b_hid, relu, dot W_post
        float tsum = 0.0f;
        #pragma unroll
        for (int nt = 0; nt < 8; nt++) {
            const float2 bh = bh2[nt * 4 + (lid & 3)];
            const float2 wp = wp2[nt * 4 + (lid & 3)];
            #pragma unroll
            for (int mt = 0; mt < 2; mt++) {
                tsum = fmaf(fmaxf(acc[mt][nt][0] + bh.x, 0.0f), wp.x, tsum);
                tsum = fmaf(fmaxf(acc[mt][nt][1] + bh.y, 0.0f), wp.y, tsum);
                tsum = fmaf(fmaxf(acc[mt][nt][2] + bh.x, 0.0f), wp.x, tsum);
                tsum = fmaf(fmaxf(acc[mt][nt][3] + bh.y, 0.0f), wp.y, tsum);
            }
        }
        acc_out += tsum;
    }

    // Deterministic reduction: warp -> block -> per-batch last CTA
    float v = acc_out;
    #pragma unroll
    for (int o = 16; o > 0; o >>= 1)
        v += __shfl_down_sync(0xffffffffu, v, o);
    if (lid == 0)
        *(float*)(smc + SM_MISC + wid * 4) = v;
    __syncthreads();
    if (tid == 0) {
        float t = 0.0f;
        #pragma unroll
        for (int w = 0; w < 4; w++)
            t += *(float*)(smc + SM_MISC + w * 4);
        g_partials[cta] = t;
        __threadfence();
        const int old = atomicAdd(&g_count[b], 1);
        if (old == CTAS_PER_BATCH - 1) {
            g_count[b] = 0;            // reset for next launch / graph replay
            __threadfence();
            const volatile float* gp = g_partials;
            float s = 0.0f;
            #pragma unroll
            for (int w = 0; w < CTAS_PER_BATCH; w++)
                s += gp[b * CTAS_PER_BATCH + w];
            out[b] = s + (float)NPTS * b_post[0];
        }
    }
}

extern "C" void kernel_launch(void* const* d_in, const int* in_sizes, int n_in,
                              void* d_out, int out_size) {
    (void)in_sizes; (void)n_in; (void)out_size;
    const float* x      = (const float*)d_in[0];
    const float* H      = (const float*)d_in[1];
    const float* W_emb  = (const float*)d_in[2];
    const float* b_emb  = (const float*)d_in[3];
    const float* W_hid  = (const float*)d_in[4];
    const float* b_hid  = (const float*)d_in[5];
    const float* W_post = (const float*)d_in[6];
    const float* b_post = (const float*)d_in[7];

    cudaFuncSetAttribute(gauge_tc, cudaFuncAttributeMaxDynamicSharedMemorySize, SMEM_BYTES);
    gauge_tc<<<NCTAS, THREADS, SMEM_BYTES>>>(x, H, W_emb, b_emb, W_hid, b_hid,
                                             W_post, b_post, (float*)d_out);
}

// round 5
// speedup vs baseline: 5.2395x; 1.2667x over previous
#include <cuda_runtime.h>
#include <cuda_fp16.h>
#include <cstdint>

#define GRIDX 128
#define NPTS (GRIDX * GRIDX)
#define HID 64
#define BATCH 64
#define TILE_M 128
#define TILES_PER_CTA 8
#define CTAS_PER_BATCH 16            // 16 * 8 * 128 = 16384 points per batch
#define NCTAS (BATCH * CTAS_PER_BATCH)
#define THREADS 128

// SMEM offsets from 1024-aligned base
#define SM_B 0                       // B: 64 rows(n) x 128B (k=j cols, swizzled), fp16
#define SM_A 8192                    // A: 128 rows(m) x 128B, fp16
#define SM_SQ 24576                  // s-quads: 128 x 16B
#define SM_WS 26624                  // wsum[4]
#define SMEM_BYTES (26624 + 64 + 1024)

#define SWZ(o) ((o) ^ (((o) >> 3) & 0x70))

__device__ float g_partials[NCTAS];
__device__ int g_count[BATCH];       // zero-init; self-resets each launch

static __device__ __forceinline__ uint32_t smem_u32(const void* p) {
    uint32_t a;
    asm("{ .reg .u64 t; cvta.to.shared.u64 t, %1; cvt.u32.u64 %0, t; }" : "=r"(a) : "l"(p));
    return a;
}
static __device__ __forceinline__ void sts32(uint32_t addr, uint32_t v) {
    asm volatile("st.shared.b32 [%0], %1;" :: "r"(addr), "r"(v) : "memory");
}
static __device__ __forceinline__ void sts64(uint32_t addr, uint32_t v0, uint32_t v1) {
    asm volatile("st.shared.v2.b32 [%0], {%1, %2};" :: "r"(addr), "r"(v0), "r"(v1) : "memory");
}
static __device__ __forceinline__ unsigned long long pack2(float lo, float hi) {
    unsigned long long r;
    asm("mov.b64 %0, {%1, %2};" : "=l"(r) : "f"(lo), "f"(hi));
    return r;
}
static __device__ __forceinline__ void unpack2(unsigned long long v, float& lo, float& hi) {
    asm("mov.b64 {%0, %1}, %2;" : "=f"(lo), "=f"(hi) : "l"(v));
}
static __device__ __forceinline__ unsigned long long ffma2(unsigned long long a,
                                                            unsigned long long b,
                                                            unsigned long long c) {
    unsigned long long d;
    asm("fma.rn.f32x2 %0, %1, %2, %3;" : "=l"(d) : "l"(a), "l"(b), "l"(c));
    return d;
}
// pack {hi_elem -> upper half, lo_elem -> lower half} as f16x2
static __device__ __forceinline__ uint32_t cvt_f16x2(float hi, float lo) {
    uint32_t r;
    asm("cvt.rn.f16x2.f32 %0, %1, %2;" : "=r"(r) : "f"(hi), "f"(lo));
    return r;
}
static __device__ __forceinline__ void ldsm_x4(uint32_t addr, uint32_t& r0, uint32_t& r1,
                                               uint32_t& r2, uint32_t& r3) {
    asm volatile("ldmatrix.sync.aligned.m8n8.x4.shared.b16 {%0,%1,%2,%3}, [%4];"
                 : "=r"(r0), "=r"(r1), "=r"(r2), "=r"(r3) : "r"(addr));
}
static __device__ __forceinline__ void mma16816(float* c, const uint32_t* a, const uint32_t* b) {
    asm volatile(
        "mma.sync.aligned.m16n8k16.row.col.f32.f16.f16.f32 "
        "{%0,%1,%2,%3}, {%4,%5,%6,%7}, {%8,%9}, {%0,%1,%2,%3};"
        : "+f"(c[0]), "+f"(c[1]), "+f"(c[2]), "+f"(c[3])
        : "r"(a[0]), "r"(a[1]), "r"(a[2]), "r"(a[3]), "r"(b[0]), "r"(b[1]));
}

__global__ __launch_bounds__(THREADS, 3)
void gauge_tc(const float* __restrict__ x, const float* __restrict__ H,
              const float* __restrict__ W_emb, const float* __restrict__ b_emb,
              const float* __restrict__ W_hid, const float* __restrict__ b_hid,
              const float* __restrict__ W_post, const float* __restrict__ b_post,
              float* __restrict__ out) {
    extern __shared__ __align__(1024) char smraw[];
    const uint32_t sb0 = smem_u32(smraw);
    const uint32_t sb = (sb0 + 1023u) & ~1023u;
    char* smc = smraw + (sb - sb0);

    const int tid = threadIdx.x;
    const int wid = tid >> 5;
    const int lid = tid & 31;

    // Build B tile: Bsm[n][j] = fp16(W_hid[j][n]), swizzled 128B rows.
    #pragma unroll
    for (int kq = 0; kq < 16; kq++) {
        const int idx = tid + kq * 128;       // 0..2047
        const int n = idx & 63;
        const int jp = idx >> 6;              // j pair 0..31
        const float w0 = __ldg(W_hid + (2 * jp) * HID + n);
        const float w1 = __ldg(W_hid + (2 * jp + 1) * HID + n);
        sts32(sb + SM_B + SWZ((uint32_t)(n * 128 + jp * 4)), cvt_f16x2(w1, w0));
    }
    __syncthreads();

    // Layer-1 per-lane weights: lane owns 4 h1 columns c0..c0+3 (16 lanes per point)
    const int c0 = (lid & 15) * 4;
    float4 wv[4];
    #pragma unroll
    for (int in = 0; in < 4; in++)
        wv[in] = __ldg((const float4*)(W_emb + in * HID + c0));
    const float4 bv = __ldg((const float4*)(b_emb + c0));

    // Epilogue per-lane: bh/wp at cols nt*8 + 2*(lid&3) + {0,1}
    float2 bhv[8], wpv[8];
    #pragma unroll
    for (int nt = 0; nt < 8; nt++) {
        bhv[nt] = __ldg((const float2*)(b_hid + nt * 8 + 2 * (lid & 3)));
        wpv[nt] = __ldg((const float2*)(W_post + nt * 8 + 2 * (lid & 3)));
    }
    const float h00 = __ldg(H + 0), h01 = __ldg(H + 1), h10 = __ldg(H + 2), h11 = __ldg(H + 3);

    const int cta = blockIdx.x;
    const int b = cta >> 4;
    const int sub = cta & 15;
    const float2* xb = (const float2*)x + (size_t)b * NPTS;

    const int warpbase = wid * 32;

    // ldmatrix lane addressing (as round 4)
    const int amat = lid >> 3;
    const int arow_base = warpbase + (amat & 1) * 8 + (lid & 7);
    const int acol_half = (amat >> 1) * 16;
    const int bn_half = (amat >> 1);
    const int bcol_half = (amat & 1) * 16;
    const int bn_sub = lid & 7;

    float acc_out = 0.0f;

    #pragma unroll 1
    for (int tt = 0; tt < TILES_PER_CTA; tt++) {
        const int base = (sub * TILES_PER_CTA + tt) * TILE_M;
        const int i = base + tid;

        __syncwarp();  // guard s-quad & A buffer reuse vs previous iteration

        // gauge contraction for this thread's point -> s-quad to smem
        {
            const int xc = i & (GRIDX - 1);
            const int yc = i >> 7;
            const int iu = xc + (((yc + 1) & (GRIDX - 1)) << 7);
            const int idn = xc + (((yc - 1) & (GRIDX - 1)) << 7);
            const int il = ((xc - 1) & (GRIDX - 1)) + (yc << 7);
            const int ir = ((xc + 1) & (GRIDX - 1)) + (yc << 7);
            const float2 xi = xb[i];
            const float2 xu = xb[iu], xd = xb[idn], xl = xb[il], xr = xb[ir];
            const float v0 = xi.x * h00 + xi.y * h10;
            const float v1 = xi.x * h01 + xi.y * h11;
            float4 sq;
            sq.x = v0 * xu.x + v1 * xu.y;
            sq.y = v0 * xd.x + v1 * xd.y;
            sq.z = v0 * xl.x + v1 * xl.y;
            sq.w = v0 * xr.x + v1 * xr.y;
            *(float4*)(smc + SM_SQ + tid * 16) = sq;
        }
        __syncwarp();

        // Layer 1: 2 points per step, 16 lanes per point, 4 cols per lane.
        #pragma unroll
        for (int q2 = 0; q2 < 16; q2++) {
            const int p = q2 * 2 + (lid >> 4);
            const int m = warpbase + p;
            const float4 sq = *(const float4*)(smc + SM_SQ + m * 16);
            unsigned long long hA = pack2(bv.x, bv.y);
            unsigned long long hB = pack2(bv.z, bv.w);
            hA = ffma2(pack2(sq.x, sq.x), pack2(wv[0].x, wv[0].y), hA);
            hB = ffma2(pack2(sq.x, sq.x), pack2(wv[0].z, wv[0].w), hB);
            hA = ffma2(pack2(sq.y, sq.y), pack2(wv[1].x, wv[1].y), hA);
            hB = ffma2(pack2(sq.y, sq.y), pack2(wv[1].z, wv[1].w), hB);
            hA = ffma2(pack2(sq.z, sq.z), pack2(wv[2].x, wv[2].y), hA);
            hB = ffma2(pack2(sq.z, sq.z), pack2(wv[2].z, wv[2].w), hB);
            hA = ffma2(pack2(sq.w, sq.w), pack2(wv[3].x, wv[3].y), hA);
            hB = ffma2(pack2(sq.w, sq.w), pack2(wv[3].z, wv[3].w), hB);
            float a0, a1, a2, a3;
            unpack2(hA, a0, a1);
            unpack2(hB, a2, a3);
            const uint32_t p0 = cvt_f16x2(fmaxf(a1, 0.0f), fmaxf(a0, 0.0f));
            const uint32_t p1 = cvt_f16x2(fmaxf(a3, 0.0f), fmaxf(a2, 0.0f));
            const uint32_t off = (uint32_t)(m * 128) +
                (((uint32_t)((lid & 15) * 8)) ^ (((uint32_t)(m & 7)) << 4));
            sts64(sb + SM_A + off, p0, p1);
        }
        __syncwarp();

        // Accumulators initialized with b_hid (C-operand of first mma)
        float acc[2][8][4];
        #pragma unroll
        for (int mt = 0; mt < 2; mt++)
            #pragma unroll
            for (int nt = 0; nt < 8; nt++) {
                acc[mt][nt][0] = bhv[nt].x;
                acc[mt][nt][1] = bhv[nt].y;
                acc[mt][nt][2] = bhv[nt].x;
                acc[mt][nt][3] = bhv[nt].y;
            }

        #pragma unroll
        for (int k = 0; k < 4; k++) {
            uint32_t af[2][4];
            #pragma unroll
            for (int mt = 0; mt < 2; mt++) {
                const int row = arow_base + mt * 16;
                const uint32_t cb = (uint32_t)(k * 32 + acol_half);
                const uint32_t off = (uint32_t)(row * 128) + (cb ^ (((uint32_t)(row & 7)) << 4));
                ldsm_x4(sb + SM_A + off, af[mt][0], af[mt][1], af[mt][2], af[mt][3]);
            }
            uint32_t bf[8][2];
            #pragma unroll
            for (int ntp = 0; ntp < 4; ntp++) {
                const int nt = ntp * 2 + bn_half;
                const int n = nt * 8 + bn_sub;
                const uint32_t cb = (uint32_t)(k * 32 + bcol_half);
                const uint32_t off = (uint32_t)(n * 128) + (cb ^ (((uint32_t)(n & 7)) << 4));
                ldsm_x4(sb + SM_B + off,
                        bf[2 * ntp][0], bf[2 * ntp][1], bf[2 * ntp + 1][0], bf[2 * ntp + 1][1]);
            }
            #pragma unroll
            for (int mt = 0; mt < 2; mt++)
                #pragma unroll
                for (int nt = 0; nt < 8; nt++)
                    mma16816(acc[mt][nt], af[mt], bf[nt]);
        }

        // Epilogue: relu, dot W_post
        float tsum = 0.0f;
        #pragma unroll
        for (int nt = 0; nt < 8; nt++) {
            #pragma unroll
            for (int mt = 0; mt < 2; mt++) {
                tsum = fmaf(fmaxf(acc[mt][nt][0], 0.0f), wpv[nt].x, tsum);
                tsum = fmaf(fmaxf(acc[mt][nt][1], 0.0f), wpv[nt].y, tsum);
                tsum = fmaf(fmaxf(acc[mt][nt][2], 0.0f), wpv[nt].x, tsum);
                tsum = fmaf(fmaxf(acc[mt][nt][3], 0.0f), wpv[nt].y, tsum);
            }
        }
        acc_out += tsum;
    }

    // Deterministic reduction: warp -> block -> per-batch last CTA
    float v = acc_out;
    #pragma unroll
    for (int o = 16; o > 0; o >>= 1)
        v += __shfl_down_sync(0xffffffffu, v, o);
    if (lid == 0)
        *(float*)(smc + SM_WS + wid * 4) = v;
    __syncthreads();
    if (tid == 0) {
        float t = 0.0f;
        #pragma unroll
        for (int w = 0; w < 4; w++)
            t += *(float*)(smc + SM_WS + w * 4);
        g_partials[cta] = t;
        __threadfence();
        const int old = atomicAdd(&g_count[b], 1);
        if (old == CTAS_PER_BATCH - 1) {
            g_count[b] = 0;            // reset for next launch / graph replay
            __threadfence();
            const volatile float* gp = g_partials;
            float s = 0.0f;
            #pragma unroll
            for (int w = 0; w < CTAS_PER_BATCH; w++)
                s += gp[b * CTAS_PER_BATCH + w];
            out[b] = s + (float)NPTS * b_post[0];
        }
    }
}

extern "C" void kernel_launch(void* const* d_in, const int* in_sizes, int n_in,
                              void* d_out, int out_size) {
    (void)in_sizes; (void)n_in; (void)out_size;
    const float* x      = (const float*)d_in[0];
    const float* H      = (const float*)d_in[1];
    const float* W_emb  = (const float*)d_in[2];
    const float* b_emb  = (const float*)d_in[3];
    const float* W_hid  = (const float*)d_in[4];
    const float* b_hid  = (const float*)d_in[5];
    const float* W_post = (const float*)d_in[6];
    const float* b_post = (const float*)d_in[7];

    cudaFuncSetAttribute(gauge_tc, cudaFuncAttributeMaxDynamicSharedMemorySize, SMEM_BYTES);
    gauge_tc<<<NCTAS, THREADS, SMEM_BYTES>>>(x, H, W_emb, b_emb, W_hid, b_hid,
                                             W_post, b_post, (float*)d_out);
}

// round 6
// speedup vs baseline: 6.7217x; 1.2829x over previous
#include <cuda_runtime.h>
#include <cuda_fp16.h>
#include <cstdint>

#define GRIDX 128
#define NPTS (GRIDX * GRIDX)
#define HID 64
#define BATCH 64
#define TILE_M 128
#define TILES_PER_CTA 8
#define CTAS_PER_BATCH 16
#define NCTAS (BATCH * CTAS_PER_BATCH)
#define THREADS 128

// SMEM offsets from 1024-aligned base
#define SM_B 0                       // B2: 64 rows(n) x 128B (k=j cols, swizzled), fp16
#define SM_SQ 8192                   // s-quads: 128 x 16B
#define SM_WS 10240                  // wsum[4]
#define SMEM_BYTES (10240 + 64 + 1024)

#define SWZ(o) ((o) ^ (((o) >> 3) & 0x70))

__device__ float g_partials[NCTAS];
__device__ int g_count[BATCH];       // zero-init; self-resets each launch

static __device__ __forceinline__ uint32_t smem_u32(const void* p) {
    uint32_t a;
    asm("{ .reg .u64 t; cvta.to.shared.u64 t, %1; cvt.u32.u64 %0, t; }" : "=r"(a) : "l"(p));
    return a;
}
static __device__ __forceinline__ void sts32(uint32_t addr, uint32_t v) {
    asm volatile("st.shared.b32 [%0], %1;" :: "r"(addr), "r"(v) : "memory");
}
// pack {hi_elem -> upper half, lo_elem -> lower half} as f16x2
static __device__ __forceinline__ uint32_t cvt_f16x2(float hi, float lo) {
    uint32_t r;
    asm("cvt.rn.f16x2.f32 %0, %1, %2;" : "=r"(r) : "f"(hi), "f"(lo));
    return r;
}
static __device__ __forceinline__ void ldsm_x4(uint32_t addr, uint32_t& r0, uint32_t& r1,
                                               uint32_t& r2, uint32_t& r3) {
    asm volatile("ldmatrix.sync.aligned.m8n8.x4.shared.b16 {%0,%1,%2,%3}, [%4];"
                 : "=r"(r0), "=r"(r1), "=r"(r2), "=r"(r3) : "r"(addr));
}
static __device__ __forceinline__ void mma16816(float* c, const uint32_t* a, const uint32_t* b) {
    asm volatile(
        "mma.sync.aligned.m16n8k16.row.col.f32.f16.f16.f32 "
        "{%0,%1,%2,%3}, {%4,%5,%6,%7}, {%8,%9}, {%0,%1,%2,%3};"
        : "+f"(c[0]), "+f"(c[1]), "+f"(c[2]), "+f"(c[3])
        : "r"(a[0]), "r"(a[1]), "r"(a[2]), "r"(a[3]), "r"(b[0]), "r"(b[1]));
}
static __device__ __forceinline__ void mma16808(float* c, const uint32_t* a, uint32_t b) {
    asm volatile(
        "mma.sync.aligned.m16n8k8.row.col.f32.f16.f16.f32 "
        "{%0,%1,%2,%3}, {%4,%5}, {%6}, {%0,%1,%2,%3};"
        : "+f"(c[0]), "+f"(c[1]), "+f"(c[2]), "+f"(c[3])
        : "r"(a[0]), "r"(a[1]), "r"(b));
}

__global__ __launch_bounds__(THREADS, 3)
void gauge_tc(const float* __restrict__ x, const float* __restrict__ H,
              const float* __restrict__ W_emb, const float* __restrict__ b_emb,
              const float* __restrict__ W_hid, const float* __restrict__ b_hid,
              const float* __restrict__ W_post, const float* __restrict__ b_post,
              float* __restrict__ out) {
    extern __shared__ __align__(1024) char smraw[];
    const uint32_t sb0 = smem_u32(smraw);
    const uint32_t sb = (sb0 + 1023u) & ~1023u;
    char* smc = smraw + (sb - sb0);

    const int tid = threadIdx.x;
    const int wid = tid >> 5;
    const int lid = tid & 31;

    // Build B2 tile: Bsm[n][j] = fp16(W_hid[j][n]), swizzled 128B rows.
    #pragma unroll
    for (int kq = 0; kq < 16; kq++) {
        const int idx = tid + kq * 128;
        const int n = idx & 63;
        const int jp = idx >> 6;
        const float w0 = __ldg(W_hid + (2 * jp) * HID + n);
        const float w1 = __ldg(W_hid + (2 * jp + 1) * HID + n);
        sts32(sb + SM_B + SWZ((uint32_t)(n * 128 + jp * 4)), cvt_f16x2(w1, w0));
    }
    __syncthreads();

    // Lane geometry
    const int r4 = lid >> 2;          // row-in-8 / n-in-8
    const int q4 = lid & 3;           // k/col pair selector
    const int kk = q4 * 2;            // k pair base (0,2,4,6); valid s only for kk<4
    const bool kvalid = (kk < 4);
    const uint32_t skoff = (uint32_t)((kk & 2) * 4);  // 0 or 8 bytes into s-quad

    // B1 fragments (m16n8k8): b = W_emb[k][n], k=(l&3)*2+{0,1}, n = nt*8 + (l>>2); 0-pad k>=4
    uint32_t b1f[8];
    #pragma unroll
    for (int nt = 0; nt < 8; nt++) {
        const int n = nt * 8 + r4;
        b1f[nt] = kvalid ? cvt_f16x2(__ldg(W_emb + (kk + 1) * HID + n),
                                     __ldg(W_emb + kk * HID + n)) : 0u;
    }
    // b_emb (C1 init), b_hid (C2 init), W_post at cols nt*8 + (l&3)*2 + {0,1}
    float2 bev[8], bhv[8], wpv[8];
    #pragma unroll
    for (int nt = 0; nt < 8; nt++) {
        bev[nt] = __ldg((const float2*)(b_emb + nt * 8 + kk));
        bhv[nt] = __ldg((const float2*)(b_hid + nt * 8 + kk));
        wpv[nt] = __ldg((const float2*)(W_post + nt * 8 + kk));
    }
    const float h00 = __ldg(H + 0), h01 = __ldg(H + 1), h10 = __ldg(H + 2), h11 = __ldg(H + 3);

    const int cta = blockIdx.x;
    const int b = cta >> 4;
    const int sub = cta & 15;
    const float2* xb = (const float2*)x + (size_t)b * NPTS;

    const int warpbase = wid * 32;

    // ldmatrix lane addressing for B2
    const int amat = lid >> 3;
    const int bn_half = (amat >> 1);
    const int bcol_half = (amat & 1) * 16;
    const int bn_sub = lid & 7;

    float acc_out = 0.0f;

    #pragma unroll 1
    for (int tt = 0; tt < TILES_PER_CTA; tt++) {
        const int base = (sub * TILES_PER_CTA + tt) * TILE_M;
        const int i = base + tid;

        __syncwarp();  // s-quad buffer reuse guard

        // gauge contraction -> s-quad to smem
        {
            const int xc = i & (GRIDX - 1);
            const int yc = i >> 7;
            const int iu = xc + (((yc + 1) & (GRIDX - 1)) << 7);
            const int idn = xc + (((yc - 1) & (GRIDX - 1)) << 7);
            const int il = ((xc - 1) & (GRIDX - 1)) + (yc << 7);
            const int ir = ((xc + 1) & (GRIDX - 1)) + (yc << 7);
            const float2 xi = xb[i];
            const float2 xu = xb[iu], xd = xb[idn], xl = xb[il], xr = xb[ir];
            const float v0 = xi.x * h00 + xi.y * h10;
            const float v1 = xi.x * h01 + xi.y * h11;
            float4 sq;
            sq.x = v0 * xu.x + v1 * xu.y;
            sq.y = v0 * xd.x + v1 * xd.y;
            sq.z = v0 * xl.x + v1 * xl.y;
            sq.w = v0 * xr.x + v1 * xr.y;
            *(float4*)(smc + SM_SQ + tid * 16) = sq;
        }
        __syncwarp();

        // Build A1 fragments (m16n8k8) straight from s-quads in smem
        uint32_t a1f[2][2];
        #pragma unroll
        for (int mt = 0; mt < 2; mt++) {
            const int row0 = warpbase + mt * 16 + r4;
            const float2 sA = *(const float2*)(smc + SM_SQ + row0 * 16 + skoff);
            const float2 sB = *(const float2*)(smc + SM_SQ + (row0 + 8) * 16 + skoff);
            a1f[mt][0] = kvalid ? cvt_f16x2(sA.y, sA.x) : 0u;
            a1f[mt][1] = kvalid ? cvt_f16x2(sB.y, sB.x) : 0u;
        }

        // Layer 1 on tensor cores: h = S @ W_emb + b_emb
        float h[2][8][4];
        #pragma unroll
        for (int mt = 0; mt < 2; mt++)
            #pragma unroll
            for (int nt = 0; nt < 8; nt++) {
                h[mt][nt][0] = bev[nt].x;
                h[mt][nt][1] = bev[nt].y;
                h[mt][nt][2] = bev[nt].x;
                h[mt][nt][3] = bev[nt].y;
                mma16808(h[mt][nt], a1f[mt], b1f[nt]);
            }

        // relu + cvt: C1 fragments become A2 fragments in registers (no smem round-trip)
        uint32_t af[2][4][4];  // [mt][k][frag]
        #pragma unroll
        for (int mt = 0; mt < 2; mt++)
            #pragma unroll
            for (int k = 0; k < 4; k++) {
                const float* hA = h[mt][2 * k];
                const float* hB = h[mt][2 * k + 1];
                af[mt][k][0] = cvt_f16x2(fmaxf(hA[1], 0.0f), fmaxf(hA[0], 0.0f));
                af[mt][k][1] = cvt_f16x2(fmaxf(hA[3], 0.0f), fmaxf(hA[2], 0.0f));
                af[mt][k][2] = cvt_f16x2(fmaxf(hB[1], 0.0f), fmaxf(hB[0], 0.0f));
                af[mt][k][3] = cvt_f16x2(fmaxf(hB[3], 0.0f), fmaxf(hB[2], 0.0f));
            }

        // Layer 2: acc = relu(h1) @ W_hid + b_hid
        float acc[2][8][4];
        #pragma unroll
        for (int mt = 0; mt < 2; mt++)
            #pragma unroll
            for (int nt = 0; nt < 8; nt++) {
                acc[mt][nt][0] = bhv[nt].x;
                acc[mt][nt][1] = bhv[nt].y;
                acc[mt][nt][2] = bhv[nt].x;
                acc[mt][nt][3] = bhv[nt].y;
            }
        #pragma unroll
        for (int k = 0; k < 4; k++) {
            uint32_t bf[8][2];
            #pragma unroll
            for (int ntp = 0; ntp < 4; ntp++) {
                const int nt = ntp * 2 + bn_half;
                const int n = nt * 8 + bn_sub;
                const uint32_t cb = (uint32_t)(k * 32 + bcol_half);
                const uint32_t off = (uint32_t)(n * 128) + (cb ^ (((uint32_t)(n & 7)) << 4));
                ldsm_x4(sb + SM_B + off,
                        bf[2 * ntp][0], bf[2 * ntp][1], bf[2 * ntp + 1][0], bf[2 * ntp + 1][1]);
            }
            #pragma unroll
            for (int mt = 0; mt < 2; mt++)
                #pragma unroll
                for (int nt = 0; nt < 8; nt++)
                    mma16816(acc[mt][nt], af[mt][k], bf[nt]);
        }

        // Epilogue: relu, dot W_post
        float tsum = 0.0f;
        #pragma unroll
        for (int nt = 0; nt < 8; nt++) {
            #pragma unroll
            for (int mt = 0; mt < 2; mt++) {
                tsum = fmaf(fmaxf(acc[mt][nt][0], 0.0f), wpv[nt].x, tsum);
                tsum = fmaf(fmaxf(acc[mt][nt][1], 0.0f), wpv[nt].y, tsum);
                tsum = fmaf(fmaxf(acc[mt][nt][2], 0.0f), wpv[nt].x, tsum);
                tsum = fmaf(fmaxf(acc[mt][nt][3], 0.0f), wpv[nt].y, tsum);
            }
        }
        acc_out += tsum;
    }

    // Deterministic reduction: warp -> block -> per-batch last CTA
    float v = acc_out;
    #pragma unroll
    for (int o = 16; o > 0; o >>= 1)
        v += __shfl_down_sync(0xffffffffu, v, o);
    if (lid == 0)
        *(float*)(smc + SM_WS + wid * 4) = v;
    __syncthreads();
    if (tid == 0) {
        float t = 0.0f;
        #pragma unroll
        for (int w = 0; w < 4; w++)
            t += *(float*)(smc + SM_WS + w * 4);
        g_partials[cta] = t;
        __threadfence();
        const int old = atomicAdd(&g_count[b], 1);
        if (old == CTAS_PER_BATCH - 1) {
            g_count[b] = 0;
            __threadfence();
            const volatile float* gp = g_partials;
            float s = 0.0f;
            #pragma unroll
            for (int w = 0; w < CTAS_PER_BATCH; w++)
                s += gp[b * CTAS_PER_BATCH + w];
            out[b] = s + (float)NPTS * b_post[0];
        }
    }
}

extern "C" void kernel_launch(void* const* d_in, const int* in_sizes, int n_in,
                              void* d_out, int out_size) {
    (void)in_sizes; (void)n_in; (void)out_size;
    const float* x      = (const float*)d_in[0];
    const float* H      = (const float*)d_in[1];
    const float* W_emb  = (const float*)d_in[2];
    const float* b_emb  = (const float*)d_in[3];
    const float* W_hid  = (const float*)d_in[4];
    const float* b_hid  = (const float*)d_in[5];
    const float* W_post = (const float*)d_in[6];
    const float* b_post = (const float*)d_in[7];

    cudaFuncSetAttribute(gauge_tc, cudaFuncAttributeMaxDynamicSharedMemorySize, SMEM_BYTES);
    gauge_tc<<<NCTAS, THREADS, SMEM_BYTES>>>(x, H, W_emb, b_emb, W_hid, b_hid,
                                             W_post, b_post, (float*)d_out);
}

// round 7
// speedup vs baseline: 6.7836x; 1.0092x over previous
#include <cuda_runtime.h>
#include <cuda_fp16.h>
#include <cstdint>

#define GRIDX 128
#define NPTS (GRIDX * GRIDX)
#define HID 64
#define BATCH 64
#define TILE_M 128
#define TILES_PER_CTA 8
#define CTAS_PER_BATCH 16
#define NCTAS (BATCH * CTAS_PER_BATCH)
#define THREADS 128

// SMEM offsets from 1024-aligned base
#define SM_B 0                       // B2: 64 rows(n) x 128B (k=j cols, swizzled), fp16
#define SM_SQ 8192                   // s-quads: 128 x 16B
#define SM_WS 10240                  // wsum[4]
#define SMEM_BYTES (10240 + 64 + 1024)

#define SWZ(o) ((o) ^ (((o) >> 3) & 0x70))
#define F16_ONE_LO 0x00003C00u       // f16x2 {hi=0, lo=1.0}

__device__ float g_partials[NCTAS];
__device__ int g_count[BATCH];       // zero-init; self-resets each launch

static __device__ __forceinline__ uint32_t smem_u32(const void* p) {
    uint32_t a;
    asm("{ .reg .u64 t; cvta.to.shared.u64 t, %1; cvt.u32.u64 %0, t; }" : "=r"(a) : "l"(p));
    return a;
}
static __device__ __forceinline__ void sts32(uint32_t addr, uint32_t v) {
    asm volatile("st.shared.b32 [%0], %1;" :: "r"(addr), "r"(v) : "memory");
}
static __device__ __forceinline__ uint32_t cvt_f16x2(float hi, float lo) {
    uint32_t r;
    asm("cvt.rn.f16x2.f32 %0, %1, %2;" : "=r"(r) : "f"(hi), "f"(lo));
    return r;
}
static __device__ __forceinline__ float f16lo_f(uint32_t v) {
    return __half2float(__ushort_as_half((unsigned short)(v & 0xffff)));
}
static __device__ __forceinline__ float f16hi_f(uint32_t v) {
    return __half2float(__ushort_as_half((unsigned short)(v >> 16)));
}
static __device__ __forceinline__ void ldsm_x4(uint32_t addr, uint32_t& r0, uint32_t& r1,
                                               uint32_t& r2, uint32_t& r3) {
    asm volatile("ldmatrix.sync.aligned.m8n8.x4.shared.b16 {%0,%1,%2,%3}, [%4];"
                 : "=r"(r0), "=r"(r1), "=r"(r2), "=r"(r3) : "r"(addr));
}
// k8 MMA, C = 0 (shared zero reg; no per-call init movs)
static __device__ __forceinline__ void mma16808_z(float* d, const uint32_t* a, uint32_t b) {
    asm volatile(
        "mma.sync.aligned.m16n8k8.row.col.f32.f16.f16.f32 "
        "{%0,%1,%2,%3}, {%4,%5}, {%6}, {%7,%7,%7,%7};"
        : "=f"(d[0]), "=f"(d[1]), "=f"(d[2]), "=f"(d[3])
        : "r"(a[0]), "r"(a[1]), "r"(b), "f"(0.0f));
}
// k16 MMA, C = {cx,cy,cx,cy} read-only (bias injection, no movs)
static __device__ __forceinline__ void mma16816_cb(float* d, const uint32_t* a,
                                                   const uint32_t* b, float cx, float cy) {
    asm volatile(
        "mma.sync.aligned.m16n8k16.row.col.f32.f16.f16.f32 "
        "{%0,%1,%2,%3}, {%4,%5,%6,%7}, {%8,%9}, {%10,%11,%10,%11};"
        : "=f"(d[0]), "=f"(d[1]), "=f"(d[2]), "=f"(d[3])
        : "r"(a[0]), "r"(a[1]), "r"(a[2]), "r"(a[3]), "r"(b[0]), "r"(b[1]),
          "f"(cx), "f"(cy));
}
// k16 MMA accumulate in place
static __device__ __forceinline__ void mma16816_acc(float* c, const uint32_t* a,
                                                    const uint32_t* b) {
    asm volatile(
        "mma.sync.aligned.m16n8k16.row.col.f32.f16.f16.f32 "
        "{%0,%1,%2,%3}, {%4,%5,%6,%7}, {%8,%9}, {%0,%1,%2,%3};"
        : "+f"(c[0]), "+f"(c[1]), "+f"(c[2]), "+f"(c[3])
        : "r"(a[0]), "r"(a[1]), "r"(a[2]), "r"(a[3]), "r"(b[0]), "r"(b[1]));
}
// k16 MMA, C = 0
static __device__ __forceinline__ void mma16816_z(float* d, const uint32_t* a,
                                                  const uint32_t* b) {
    asm volatile(
        "mma.sync.aligned.m16n8k16.row.col.f32.f16.f16.f32 "
        "{%0,%1,%2,%3}, {%4,%5,%6,%7}, {%8,%9}, {%10,%10,%10,%10};"
        : "=f"(d[0]), "=f"(d[1]), "=f"(d[2]), "=f"(d[3])
        : "r"(a[0]), "r"(a[1]), "r"(a[2]), "r"(a[3]), "r"(b[0]), "r"(b[1]),
          "f"(0.0f));
}

__global__ __launch_bounds__(THREADS, 4)
void gauge_tc(const float* __restrict__ x, const float* __restrict__ H,
              const float* __restrict__ W_emb, const float* __restrict__ b_emb,
              const float* __restrict__ W_hid, const float* __restrict__ b_hid,
              const float* __restrict__ W_post, const float* __restrict__ b_post,
              float* __restrict__ out) {
    extern __shared__ __align__(1024) char smraw[];
    const uint32_t sb0 = smem_u32(smraw);
    const uint32_t sb = (sb0 + 1023u) & ~1023u;
    char* smc = smraw + (sb - sb0);

    const int tid = threadIdx.x;
    const int wid = tid >> 5;
    const int lid = tid & 31;

    // Build B2 tile: Bsm[n][j] = fp16(W_hid[j][n]), swizzled 128B rows.
    #pragma unroll
    for (int kq = 0; kq < 16; kq++) {
        const int idx = tid + kq * 128;
        const int n = idx & 63;
        const int jp = idx >> 6;
        const float w0 = __ldg(W_hid + (2 * jp) * HID + n);
        const float w1 = __ldg(W_hid + (2 * jp + 1) * HID + n);
        sts32(sb + SM_B + SWZ((uint32_t)(n * 128 + jp * 4)), cvt_f16x2(w1, w0));
    }
    __syncthreads();

    // Lane geometry
    const int r4 = lid >> 2;                    // row-in-8 / n index
    const int q4 = lid & 3;                     // k/col pair selector
    const int kk = q4 * 2;                      // pair base 0,2,4,6
    const uint32_t skoff = (uint32_t)((kk & 2) * 4);

    // Layer-1 B frags (m16n8k8, K padded to 8): k=0..3 -> W_emb, k=4 -> b_emb (bias row), k>=5 -> 0
    uint32_t b1f[8];
    #pragma unroll
    for (int nt = 0; nt < 8; nt++) {
        const int n = nt * 8 + r4;
        float lo_w, hi_w;
        if (q4 < 2)       { lo_w = __ldg(W_emb + kk * HID + n); hi_w = __ldg(W_emb + (kk + 1) * HID + n); }
        else if (q4 == 2) { lo_w = __ldg(b_emb + n); hi_w = 0.0f; }
        else              { lo_w = 0.0f; hi_w = 0.0f; }
        b1f[nt] = cvt_f16x2(hi_w, lo_w);
    }

    // b_hid at C-frag cols nt*8 + kk + {0,1}
    float2 bhv[8];
    #pragma unroll
    for (int nt = 0; nt < 8; nt++)
        bhv[nt] = __ldg((const float2*)(b_hid + nt * 8 + kk));

    // W_post B-frags for epilogue MMA: n=0 col = wp_hi, n=1 col = wp_lo, else 0
    uint32_t wpb[4][2];
    #pragma unroll
    for (int k = 0; k < 4; k++) {
        const int j = k * 16 + kk;
        const float2 w0 = __ldg((const float2*)(W_post + j));
        const float2 w1 = __ldg((const float2*)(W_post + j + 8));
        const uint32_t h0 = cvt_f16x2(w0.y, w0.x);
        const uint32_t h1 = cvt_f16x2(w1.y, w1.x);
        if (r4 == 0)      { wpb[k][0] = h0; wpb[k][1] = h1; }
        else if (r4 == 1) {
            wpb[k][0] = cvt_f16x2(w0.y - f16hi_f(h0), w0.x - f16lo_f(h0));
            wpb[k][1] = cvt_f16x2(w1.y - f16hi_f(h1), w1.x - f16lo_f(h1));
        } else            { wpb[k][0] = 0u; wpb[k][1] = 0u; }
    }
    const float h00 = __ldg(H + 0), h01 = __ldg(H + 1), h10 = __ldg(H + 2), h11 = __ldg(H + 3);

    const int cta = blockIdx.x;
    const int b = cta >> 4;
    const int sub = cta & 15;
    const float2* xb = (const float2*)x + (size_t)b * NPTS;

    const int warpbase = wid * 32;

    // ldmatrix lane addressing for B2
    const int amat = lid >> 3;
    const int bn_half = (amat >> 1);
    const int bcol_half = (amat & 1) * 16;
    const int bn_sub = lid & 7;

    float acc_out = 0.0f;

    #pragma unroll 1
    for (int tt = 0; tt < TILES_PER_CTA; tt++) {
        const int base = (sub * TILES_PER_CTA + tt) * TILE_M;
        const int i = base + tid;

        __syncwarp();  // s-quad buffer reuse guard

        // gauge contraction -> s-quad to smem
        {
            const int xc = i & (GRIDX - 1);
            const int yc = i >> 7;
            const int iu = xc + (((yc + 1) & (GRIDX - 1)) << 7);
            const int idn = xc + (((yc - 1) & (GRIDX - 1)) << 7);
            const int il = ((xc - 1) & (GRIDX - 1)) + (yc << 7);
            const int ir = ((xc + 1) & (GRIDX - 1)) + (yc << 7);
            const float2 xi = xb[i];
            const float2 xu = xb[iu], xd = xb[idn], xl = xb[il], xr = xb[ir];
            const float v0 = xi.x * h00 + xi.y * h10;
            const float v1 = xi.x * h01 + xi.y * h11;
            float4 sq;
            sq.x = v0 * xu.x + v1 * xu.y;
            sq.y = v0 * xd.x + v1 * xd.y;
            sq.z = v0 * xl.x + v1 * xl.y;
            sq.w = v0 * xr.x + v1 * xr.y;
            *(float4*)(smc + SM_SQ + tid * 16) = sq;
        }
        __syncwarp();

        float tsum = 0.0f;

        #pragma unroll 1
        for (int mt = 0; mt < 2; mt++) {
            // A1 fragments (K=8 pad: k4 = 1.0 bias lane, k>=5 = 0)
            const int row0 = warpbase + mt * 16 + r4;
            const float2 sA = *(const float2*)(smc + SM_SQ + row0 * 16 + skoff);
            const float2 sB = *(const float2*)(smc + SM_SQ + (row0 + 8) * 16 + skoff);
            uint32_t a1f[2];
            if (q4 < 2) { a1f[0] = cvt_f16x2(sA.y, sA.x); a1f[1] = cvt_f16x2(sB.y, sB.x); }
            else if (q4 == 2) { a1f[0] = F16_ONE_LO; a1f[1] = F16_ONE_LO; }
            else { a1f[0] = 0u; a1f[1] = 0u; }

            // Layer 1: h = [S|1] @ [W_emb; b_emb]  (C = 0, bias via K)
            float h[8][4];
            #pragma unroll
            for (int nt = 0; nt < 8; nt++)
                mma16808_z(h[nt], a1f, b1f[nt]);

            // relu + cvt: C1 frags -> A2 frags in registers
            uint32_t af[4][4];
            #pragma unroll
            for (int k = 0; k < 4; k++) {
                const float* hA = h[2 * k];
                const float* hB = h[2 * k + 1];
                af[k][0] = cvt_f16x2(fmaxf(hA[1], 0.0f), fmaxf(hA[0], 0.0f));
                af[k][1] = cvt_f16x2(fmaxf(hA[3], 0.0f), fmaxf(hA[2], 0.0f));
                af[k][2] = cvt_f16x2(fmaxf(hB[1], 0.0f), fmaxf(hB[0], 0.0f));
                af[k][3] = cvt_f16x2(fmaxf(hB[3], 0.0f), fmaxf(hB[2], 0.0f));
            }

            // Layer 2: acc = relu(h1) @ W_hid + b_hid (bias as k=0 C operand)
            float acc[8][4];
            #pragma unroll
            for (int k = 0; k < 4; k++) {
                uint32_t bf[8][2];
                #pragma unroll
                for (int ntp = 0; ntp < 4; ntp++) {
                    const int nt = ntp * 2 + bn_half;
                    const int n = nt * 8 + bn_sub;
                    const uint32_t cb = (uint32_t)(k * 32 + bcol_half);
                    const uint32_t off = (uint32_t)(n * 128) + (cb ^ (((uint32_t)(n & 7)) << 4));
                    ldsm_x4(sb + SM_B + off,
                            bf[2 * ntp][0], bf[2 * ntp][1], bf[2 * ntp + 1][0], bf[2 * ntp + 1][1]);
                }
                if (k == 0) {
                    #pragma unroll
                    for (int nt = 0; nt < 8; nt++)
                        mma16816_cb(acc[nt], af[0], bf[nt], bhv[nt].x, bhv[nt].y);
                } else {
                    #pragma unroll
                    for (int nt = 0; nt < 8; nt++)
                        mma16816_acc(acc[nt], af[k], bf[nt]);
                }
            }

            // Epilogue on tensor: relu(acc) C-frags -> A-frags; B = [wp_hi, wp_lo, 0...]
            uint32_t af3[4][4];
            #pragma unroll
            for (int k = 0; k < 4; k++) {
                const float* cA = acc[2 * k];
                const float* cB = acc[2 * k + 1];
                af3[k][0] = cvt_f16x2(fmaxf(cA[1], 0.0f), fmaxf(cA[0], 0.0f));
                af3[k][1] = cvt_f16x2(fmaxf(cA[3], 0.0f), fmaxf(cA[2], 0.0f));
                af3[k][2] = cvt_f16x2(fmaxf(cB[1], 0.0f), fmaxf(cB[0], 0.0f));
                af3[k][3] = cvt_f16x2(fmaxf(cB[3], 0.0f), fmaxf(cB[2], 0.0f));
            }
            float ds[4];
            mma16816_z(ds, af3[0], wpb[0]);
            #pragma unroll
            for (int k = 1; k < 4; k++)
                mma16816_acc(ds, af3[k], wpb[k]);
            // cols 0 (hi) + 1 (lo) live in lanes with q4==0; rows r4 and r4+8
            const float g = (ds[0] + ds[1]) + (ds[2] + ds[3]);
            tsum += (q4 == 0) ? g : 0.0f;
        }
        acc_out += tsum;
    }

    // Deterministic reduction: warp -> block -> per-batch last CTA
    float v = acc_out;
    #pragma unroll
    for (int o = 16; o > 0; o >>= 1)
        v += __shfl_down_sync(0xffffffffu, v, o);
    if (lid == 0)
        *(float*)(smc + SM_WS + wid * 4) = v;
    __syncthreads();
    if (tid == 0) {
        float t = 0.0f;
        #pragma unroll
        for (int w = 0; w < 4; w++)
            t += *(float*)(smc + SM_WS + w * 4);
        g_partials[cta] = t;
        __threadfence();
        const int old = atomicAdd(&g_count[b], 1);
        if (old == CTAS_PER_BATCH - 1) {
            g_count[b] = 0;
            __threadfence();
            const volatile float* gp = g_partials;
            float s = 0.0f;
            #pragma unroll
            for (int w = 0; w < CTAS_PER_BATCH; w++)
                s += gp[b * CTAS_PER_BATCH + w];
            out[b] = s + (float)NPTS * b_post[0];
        }
    }
}

extern "C" void kernel_launch(void* const* d_in, const int* in_sizes, int n_in,
                              void* d_out, int out_size) {
    (void)in_sizes; (void)n_in; (void)out_size;
    const float* x      = (const float*)d_in[0];
    const float* H      = (const float*)d_in[1];
    const float* W_emb  = (const float*)d_in[2];
    const float* b_emb  = (const float*)d_in[3];
    const float* W_hid  = (const float*)d_in[4];
    const float* b_hid  = (const float*)d_in[5];
    const float* W_post = (const float*)d_in[6];
    const float* b_post = (const float*)d_in[7];

    cudaFuncSetAttribute(gauge_tc, cudaFuncAttributeMaxDynamicSharedMemorySize, SMEM_BYTES);
    gauge_tc<<<NCTAS, THREADS, SMEM_BYTES>>>(x, H, W_emb, b_emb, W_hid, b_hid,
                                             W_post, b_post, (float*)d_out);
}

// round 8
// speedup vs baseline: 6.8202x; 1.0054x over previous
#include <cuda_runtime.h>
#include <cuda_fp16.h>
#include <cstdint>

#define GRIDX 128
#define NPTS (GRIDX * GRIDX)
#define HID 64
#define BATCH 64
#define TILE_M 128
#define TILES_PER_CTA 8
#define CTAS_PER_BATCH 16
#define NCTAS (BATCH * CTAS_PER_BATCH)
#define THREADS 128

// SMEM offsets from 1024-aligned base
#define SM_B 0                       // B2: 64 rows(n) x 128B (k=j cols, swizzled), fp16
#define SM_SQ 8192                   // s-quads: 128 x 16B
#define SM_WS 10240                  // wsum[4]
#define SMEM_BYTES (10240 + 64 + 1024)

#define SWZ(o) ((o) ^ (((o) >> 3) & 0x70))
#define F16_ONE_LO 0x00003C00u       // f16x2 {hi=0, lo=1.0}

__device__ float g_partials[NCTAS];
__device__ int g_count[BATCH];       // zero-init; self-resets each launch

static __device__ __forceinline__ uint32_t smem_u32(const void* p) {
    uint32_t a;
    asm("{ .reg .u64 t; cvta.to.shared.u64 t, %1; cvt.u32.u64 %0, t; }" : "=r"(a) : "l"(p));
    return a;
}
static __device__ __forceinline__ void sts32(uint32_t addr, uint32_t v) {
    asm volatile("st.shared.b32 [%0], %1;" :: "r"(addr), "r"(v) : "memory");
}
static __device__ __forceinline__ uint32_t cvt_f16x2(float hi, float lo) {
    uint32_t r;
    asm("cvt.rn.f16x2.f32 %0, %1, %2;" : "=r"(r) : "f"(hi), "f"(lo));
    return r;
}
static __device__ __forceinline__ uint32_t relu2(uint32_t v) {
    uint32_t r;
    asm("max.f16x2 %0, %1, %2;" : "=r"(r) : "r"(v), "r"(0u));
    return r;
}
static __device__ __forceinline__ float f16lo_f(uint32_t v) {
    return __half2float(__ushort_as_half((unsigned short)(v & 0xffff)));
}
static __device__ __forceinline__ float f16hi_f(uint32_t v) {
    return __half2float(__ushort_as_half((unsigned short)(v >> 16)));
}
static __device__ __forceinline__ void ldsm_x4(uint32_t addr, uint32_t& r0, uint32_t& r1,
                                               uint32_t& r2, uint32_t& r3) {
    asm volatile("ldmatrix.sync.aligned.m8n8.x4.shared.b16 {%0,%1,%2,%3}, [%4];"
                 : "=r"(r0), "=r"(r1), "=r"(r2), "=r"(r3) : "r"(addr));
}
static __device__ __forceinline__ void mma16808_z(float* d, const uint32_t* a, uint32_t b) {
    asm volatile(
        "mma.sync.aligned.m16n8k8.row.col.f32.f16.f16.f32 "
        "{%0,%1,%2,%3}, {%4,%5}, {%6}, {%7,%7,%7,%7};"
        : "=f"(d[0]), "=f"(d[1]), "=f"(d[2]), "=f"(d[3])
        : "r"(a[0]), "r"(a[1]), "r"(b), "f"(0.0f));
}
static __device__ __forceinline__ void mma16816_cb(float* d, const uint32_t* a,
                                                   const uint32_t* b, float cx, float cy) {
    asm volatile(
        "mma.sync.aligned.m16n8k16.row.col.f32.f16.f16.f32 "
        "{%0,%1,%2,%3}, {%4,%5,%6,%7}, {%8,%9}, {%10,%11,%10,%11};"
        : "=f"(d[0]), "=f"(d[1]), "=f"(d[2]), "=f"(d[3])
        : "r"(a[0]), "r"(a[1]), "r"(a[2]), "r"(a[3]), "r"(b[0]), "r"(b[1]),
          "f"(cx), "f"(cy));
}
static __device__ __forceinline__ void mma16816_acc(float* c, const uint32_t* a,
                                                    const uint32_t* b) {
    asm volatile(
        "mma.sync.aligned.m16n8k16.row.col.f32.f16.f16.f32 "
        "{%0,%1,%2,%3}, {%4,%5,%6,%7}, {%8,%9}, {%0,%1,%2,%3};"
        : "+f"(c[0]), "+f"(c[1]), "+f"(c[2]), "+f"(c[3])
        : "r"(a[0]), "r"(a[1]), "r"(a[2]), "r"(a[3]), "r"(b[0]), "r"(b[1]));
}
static __device__ __forceinline__ void mma16816_z(float* d, const uint32_t* a,
                                                  const uint32_t* b) {
    asm volatile(
        "mma.sync.aligned.m16n8k16.row.col.f32.f16.f16.f32 "
        "{%0,%1,%2,%3}, {%4,%5,%6,%7}, {%8,%9}, {%10,%10,%10,%10};"
        : "=f"(d[0]), "=f"(d[1]), "=f"(d[2]), "=f"(d[3])
        : "r"(a[0]), "r"(a[1]), "r"(a[2]), "r"(a[3]), "r"(b[0]), "r"(b[1]),
          "f"(0.0f));
}

__global__ __launch_bounds__(THREADS, 3)
void gauge_tc(const float* __restrict__ x, const float* __restrict__ H,
              const float* __restrict__ W_emb, const float* __restrict__ b_emb,
              const float* __restrict__ W_hid, const float* __restrict__ b_hid,
              const float* __restrict__ W_post, const float* __restrict__ b_post,
              float* __restrict__ out) {
    extern __shared__ __align__(1024) char smraw[];
    const uint32_t sb0 = smem_u32(smraw);
    const uint32_t sb = (sb0 + 1023u) & ~1023u;
    char* smc = smraw + (sb - sb0);

    const int tid = threadIdx.x;
    const int wid = tid >> 5;
    const int lid = tid & 31;

    // Build B2 tile in smem: Bsm[n][j] = fp16(W_hid[j][n]), swizzled 128B rows.
    #pragma unroll
    for (int kq = 0; kq < 16; kq++) {
        const int idx = tid + kq * 128;
        const int n = idx & 63;
        const int jp = idx >> 6;
        const float w0 = __ldg(W_hid + (2 * jp) * HID + n);
        const float w1 = __ldg(W_hid + (2 * jp + 1) * HID + n);
        sts32(sb + SM_B + SWZ((uint32_t)(n * 128 + jp * 4)), cvt_f16x2(w1, w0));
    }
    __syncthreads();

    // Lane geometry
    const int r4 = lid >> 2;
    const int q4 = lid & 3;
    const int kk = q4 * 2;
    const uint32_t skoff = (uint32_t)((kk & 2) * 4);

    // Hoisted B2 fragments (loop-invariant): 4 k-steps x 8 n-tiles x 2 regs = 64 regs
    uint32_t bf2[4][8][2];
    {
        const int amat = lid >> 3;
        const int bn_half = (amat >> 1);
        const int bcol_half = (amat & 1) * 16;
        const int bn_sub = lid & 7;
        #pragma unroll
        for (int k = 0; k < 4; k++) {
            #pragma unroll
            for (int ntp = 0; ntp < 4; ntp++) {
                const int nt = ntp * 2 + bn_half;
                const int n = nt * 8 + bn_sub;
                const uint32_t cb = (uint32_t)(k * 32 + bcol_half);
                const uint32_t off = (uint32_t)(n * 128) + (cb ^ (((uint32_t)(n & 7)) << 4));
                ldsm_x4(sb + SM_B + off, bf2[k][2 * ntp][0], bf2[k][2 * ntp][1],
                        bf2[k][2 * ntp + 1][0], bf2[k][2 * ntp + 1][1]);
            }
        }
    }

    // Layer-1 B frags (m16n8k8, K padded to 8): k=0..3 W_emb, k=4 b_emb, k>=5 zero
    uint32_t b1f[8];
    #pragma unroll
    for (int nt = 0; nt < 8; nt++) {
        const int n = nt * 8 + r4;
        float lo_w, hi_w;
        if (q4 < 2)       { lo_w = __ldg(W_emb + kk * HID + n); hi_w = __ldg(W_emb + (kk + 1) * HID + n); }
        else if (q4 == 2) { lo_w = __ldg(b_emb + n); hi_w = 0.0f; }
        else              { lo_w = 0.0f; hi_w = 0.0f; }
        b1f[nt] = cvt_f16x2(hi_w, lo_w);
    }

    // b_hid at C-frag cols nt*8 + kk + {0,1}
    float2 bhv[8];
    #pragma unroll
    for (int nt = 0; nt < 8; nt++)
        bhv[nt] = __ldg((const float2*)(b_hid + nt * 8 + kk));

    // W_post epilogue B-frags: n=0 col = wp_hi, n=1 col = wp_lo residual, else 0
    uint32_t wpb[4][2];
    #pragma unroll
    for (int k = 0; k < 4; k++) {
        const int j = k * 16 + kk;
        const float2 w0 = __ldg((const float2*)(W_post + j));
        const float2 w1 = __ldg((const float2*)(W_post + j + 8));
        const uint32_t h0 = cvt_f16x2(w0.y, w0.x);
        const uint32_t h1 = cvt_f16x2(w1.y, w1.x);
        if (r4 == 0)      { wpb[k][0] = h0; wpb[k][1] = h1; }
        else if (r4 == 1) {
            wpb[k][0] = cvt_f16x2(w0.y - f16hi_f(h0), w0.x - f16lo_f(h0));
            wpb[k][1] = cvt_f16x2(w1.y - f16hi_f(h1), w1.x - f16lo_f(h1));
        } else            { wpb[k][0] = 0u; wpb[k][1] = 0u; }
    }
    const float h00 = __ldg(H + 0), h01 = __ldg(H + 1), h10 = __ldg(H + 2), h11 = __ldg(H + 3);

    const int cta = blockIdx.x;
    const int b = cta >> 4;
    const int sub = cta & 15;
    const float2* xb = (const float2*)x + (size_t)b * NPTS;
    const int warpbase = wid * 32;

    float acc_out = 0.0f;

    #pragma unroll 1
    for (int tt = 0; tt < TILES_PER_CTA; tt++) {
        const int base = (sub * TILES_PER_CTA + tt) * TILE_M;
        const int i = base + tid;

        __syncwarp();  // s-quad buffer reuse guard

        // gauge contraction -> s-quad to smem
        {
            const int xc = i & (GRIDX - 1);
            const int yc = i >> 7;
            const int iu = xc + (((yc + 1) & (GRIDX - 1)) << 7);
            const int idn = xc + (((yc - 1) & (GRIDX - 1)) << 7);
            const int il = ((xc - 1) & (GRIDX - 1)) + (yc << 7);
            const int ir = ((xc + 1) & (GRIDX - 1)) + (yc << 7);
            const float2 xi = xb[i];
            const float2 xu = xb[iu], xd = xb[idn], xl = xb[il], xr = xb[ir];
            const float v0 = xi.x * h00 + xi.y * h10;
            const float v1 = xi.x * h01 + xi.y * h11;
            float4 sq;
            sq.x = v0 * xu.x + v1 * xu.y;
            sq.y = v0 * xd.x + v1 * xd.y;
            sq.z = v0 * xl.x + v1 * xl.y;
            sq.w = v0 * xr.x + v1 * xr.y;
            *(float4*)(smc + SM_SQ + tid * 16) = sq;
        }
        __syncwarp();

        float tsum = 0.0f;

        #pragma unroll 1
        for (int mt = 0; mt < 2; mt++) {
            // A1 fragments (K=8 pad: k4 = 1.0 bias lane, k>=5 = 0)
            const int row0 = warpbase + mt * 16 + r4;
            const float2 sA = *(const float2*)(smc + SM_SQ + row0 * 16 + skoff);
            const float2 sB = *(const float2*)(smc + SM_SQ + (row0 + 8) * 16 + skoff);
            uint32_t a1f[2];
            if (q4 < 2) { a1f[0] = cvt_f16x2(sA.y, sA.x); a1f[1] = cvt_f16x2(sB.y, sB.x); }
            else if (q4 == 2) { a1f[0] = F16_ONE_LO; a1f[1] = F16_ONE_LO; }
            else { a1f[0] = 0u; a1f[1] = 0u; }

            // Layer 1: h = [S|1] @ [W_emb; b_emb]
            float h[8][4];
            #pragma unroll
            for (int nt = 0; nt < 8; nt++)
                mma16808_z(h[nt], a1f, b1f[nt]);

            // cvt then relu in fp16 (max.f16x2): C1 frags -> A2 frags
            uint32_t af[4][4];
            #pragma unroll
            for (int k = 0; k < 4; k++) {
                const float* hA = h[2 * k];
                const float* hB = h[2 * k + 1];
                af[k][0] = relu2(cvt_f16x2(hA[1], hA[0]));
                af[k][1] = relu2(cvt_f16x2(hA[3], hA[2]));
                af[k][2] = relu2(cvt_f16x2(hB[1], hB[0]));
                af[k][3] = relu2(cvt_f16x2(hB[3], hB[2]));
            }

            // Layer 2: acc = relu(h1) @ W_hid + b_hid (hoisted B frags, no LDSM)
            float acc[8][4];
            #pragma unroll
            for (int nt = 0; nt < 8; nt++)
                mma16816_cb(acc[nt], af[0], bf2[0][nt], bhv[nt].x, bhv[nt].y);
            #pragma unroll
            for (int k = 1; k < 4; k++)
                #pragma unroll
                for (int nt = 0; nt < 8; nt++)
                    mma16816_acc(acc[nt], af[k], bf2[k][nt]);

            // Epilogue: relu(acc) -> A-frags; dot W_post via MMA (cols 0/1 = hi/lo)
            uint32_t af3[4][4];
            #pragma unroll
            for (int k = 0; k < 4; k++) {
                const float* cA = acc[2 * k];
                const float* cB = acc[2 * k + 1];
                af3[k][0] = relu2(cvt_f16x2(cA[1], cA[0]));
                af3[k][1] = relu2(cvt_f16x2(cA[3], cA[2]));
                af3[k][2] = relu2(cvt_f16x2(cB[1], cB[0]));
                af3[k][3] = relu2(cvt_f16x2(cB[3], cB[2]));
            }
            float ds[4];
            mma16816_z(ds, af3[0], wpb[0]);
            #pragma unroll
            for (int k = 1; k < 4; k++)
                mma16816_acc(ds, af3[k], wpb[k]);
            const float g = (ds[0] + ds[1]) + (ds[2] + ds[3]);
            tsum += (q4 == 0) ? g : 0.0f;
        }
        acc_out += tsum;
    }

    // Deterministic reduction: warp -> block -> per-batch last CTA
    float v = acc_out;
    #pragma unroll
    for (int o = 16; o > 0; o >>= 1)
        v += __shfl_down_sync(0xffffffffu, v, o);
    if (lid == 0)
        *(float*)(smc + SM_WS + wid * 4) = v;
    __syncthreads();
    if (tid == 0) {
        float t = 0.0f;
        #pragma unroll
        for (int w = 0; w < 4; w++)
            t += *(float*)(smc + SM_WS + w * 4);
        g_partials[cta] = t;
        __threadfence();
        const int old = atomicAdd(&g_count[b], 1);
        if (old == CTAS_PER_BATCH - 1) {
            g_count[b] = 0;
            __threadfence();
            const volatile float* gp = g_partials;
            float s = 0.0f;
            #pragma unroll
            for (int w = 0; w < CTAS_PER_BATCH; w++)
                s += gp[b * CTAS_PER_BATCH + w];
            out[b] = s + (float)NPTS * b_post[0];
        }
    }
}

extern "C" void kernel_launch(void* const* d_in, const int* in_sizes, int n_in,
                              void* d_out, int out_size) {
    (void)in_sizes; (void)n_in; (void)out_size;
    const float* x      = (const float*)d_in[0];
    const float* H      = (const float*)d_in[1];
    const float* W_emb  = (const float*)d_in[2];
    const float* b_emb  = (const float*)d_in[3];
    const float* W_hid  = (const float*)d_in[4];
    const float* b_hid  = (const float*)d_in[5];
    const float* W_post = (const float*)d_in[6];
    const float* b_post = (const float*)d_in[7];

    cudaFuncSetAttribute(gauge_tc, cudaFuncAttributeMaxDynamicSharedMemorySize, SMEM_BYTES);
    gauge_tc<<<NCTAS, THREADS, SMEM_BYTES>>>(x, H, W_emb, b_emb, W_hid, b_hid,
                                             W_post, b_post, (float*)d_out);
}